// round 8
// baseline (speedup 1.0000x reference)
#include <cuda_runtime.h>
#include <cfloat>

#define NB    2
#define CC    256
#define HH    64
#define WW    64
#define KK    128
#define PH    7
#define PW    7
#define CPB   32           // channels per block in pooling kernel
#define CGRP  (CC / CPB)   // 8 channel groups

// NHWC scratch: [2, 64, 64, 256] floats = 8.4 MB (static device array: no allocation)
__device__ float g_xt[NB * HH * WW * CC];

// ---------------- Kernel 1: NCHW -> NHWC transpose ----------------
// View per batch: [256, 4096] -> [4096, 256]
__global__ __launch_bounds__(256) void transpose_kernel(const float* __restrict__ x)
{
    __shared__ float tile[32][33];
    int b   = blockIdx.z;
    int hw0 = blockIdx.x * 32;   // 4096 / 32 = 128
    int c0  = blockIdx.y * 32;   // 256  / 32 = 8

    const float* src = x    + (size_t)b * CC * (HH * WW);
    float*       dst = g_xt + (size_t)b * (HH * WW) * CC;

    #pragma unroll
    for (int i = 0; i < 4; ++i) {
        int c = c0 + threadIdx.y + i * 8;
        tile[threadIdx.y + i * 8][threadIdx.x] = src[(size_t)c * (HH * WW) + hw0 + threadIdx.x];
    }
    __syncthreads();
    #pragma unroll
    for (int i = 0; i < 4; ++i) {
        int hw = hw0 + threadIdx.y + i * 8;
        dst[(size_t)hw * CC + c0 + threadIdx.x] = tile[threadIdx.x][threadIdx.y + i * 8];
    }
}

// ---------------- Kernel 2: ROI max-pool over NHWC ----------------
// Block = (k, channel group of 32). 8 warps; warp takes bins t = warp, warp+8, ...
// Lane = channel within group -> every pixel visit is one aligned 128B LDG.
__global__ __launch_bounds__(256) void roipool_nhwc_kernel(
    const float* __restrict__ rois,  // [K, 5]
    float* __restrict__ out)         // [K, C, 7, 7]
{
    __shared__ float stage[CPB * PH * PW];  // [c_local][bin], stride 49 -> conflict-free

    int k    = blockIdx.x >> 3;     // /CGRP
    int cg   = blockIdx.x & 7;      // %CGRP
    int warp = threadIdx.x >> 5;
    int lane = threadIdx.x & 31;

    const float* r = rois + k * 5;
    int b  = (int)r[0];
    // IEEE RN multiply (0.0625 exact), round half-to-even like jnp.round
    int x1 = (int)rintf(__fmul_rn(r[1], 0.0625f));
    int y1 = (int)rintf(__fmul_rn(r[2], 0.0625f));
    int x2 = (int)rintf(__fmul_rn(r[3], 0.0625f));
    int y2 = (int)rintf(__fmul_rn(r[4], 0.0625f));

    int roi_w = max(x2 - x1 + 1, 1);
    int roi_h = max(y2 - y1 + 1, 1);

    // XLA rewrites (x / 7) -> x * RN(1/7); RN(1/7) = 0x3E124925
    const float RECIP7 = __int_as_float(0x3E124925);
    float bw = __fmul_rn((float)roi_w, RECIP7);
    float bh = __fmul_rn((float)roi_h, RECIP7);

    const float* base = g_xt + (size_t)b * (HH * WW) * CC + cg * CPB;

    for (int t = warp; t < PH * PW; t += 8) {
        int i = t / PW;
        int j = t - i * PW;

        int hs = min(max((int)floorf(__fmul_rn((float)i,       bh)) + y1, 0), HH);
        int he = min(max((int)ceilf (__fmul_rn((float)(i + 1), bh)) + y1, 0), HH);
        int ws = min(max((int)floorf(__fmul_rn((float)j,       bw)) + x1, 0), WW);
        int we = min(max((int)ceilf (__fmul_rn((float)(j + 1), bw)) + x1, 0), WW);

        float acc;
        if (hs < he && ws < we) {
            acc = -FLT_MAX;
            for (int h = hs; h < he; ++h) {
                const float* rowp = base + (size_t)(h * WW) * CC + lane;
                int w = ws;
                for (; w + 1 < we; w += 2) {
                    float v0 = __ldg(rowp + (size_t)w       * CC);
                    float v1 = __ldg(rowp + (size_t)(w + 1) * CC);
                    acc = fmaxf(acc, fmaxf(v0, v1));
                }
                if (w < we) acc = fmaxf(acc, __ldg(rowp + (size_t)w * CC));
            }
        } else {
            acc = 0.0f;  // empty bin -> 0 per reference
        }
        stage[lane * (PH * PW) + t] = acc;
    }
    __syncthreads();

    // Coalesced store: chunk of 32 channels x 49 bins, contiguous in out
    float* o = out + (size_t)k * (CC * PH * PW) + (size_t)cg * (CPB * PH * PW);
    for (int idx = threadIdx.x; idx < CPB * PH * PW; idx += 256)
        o[idx] = stage[idx];
}

extern "C" void kernel_launch(void* const* d_in, const int* in_sizes, int n_in,
                              void* d_out, int out_size)
{
    const float* x    = (const float*)d_in[0];
    const float* rois = (const float*)d_in[1];
    if (n_in >= 2 && in_sizes[0] < in_sizes[1]) {
        x    = (const float*)d_in[1];
        rois = (const float*)d_in[0];
    }
    float* out = (float*)d_out;

    dim3 tgrid(HH * WW / 32, CC / 32, NB);   // (128, 8, 2)
    dim3 tblk(32, 8);
    transpose_kernel<<<tgrid, tblk>>>(x);

    roipool_nhwc_kernel<<<KK * CGRP, 256>>>(rois, out);  // 1024 blocks
}

// round 9
// speedup vs baseline: 2.2705x; 2.2705x over previous
#include <cuda_runtime.h>
#include <cfloat>

#define NB    2
#define CC    256
#define HH    64
#define WW    64
#define KK    128
#define PH    7
#define PW    7

// NHWC scratch: [2, 64, 64, 256] floats = 8.4 MB
__device__ float g_xt[NB * HH * WW * CC];

// ---------------- Kernel 1: NCHW -> NHWC transpose ----------------
__global__ __launch_bounds__(256) void transpose_kernel(const float* __restrict__ x)
{
    __shared__ float tile[32][33];
    int b   = blockIdx.z;
    int hw0 = blockIdx.x * 32;
    int c0  = blockIdx.y * 32;

    const float* src = x    + (size_t)b * CC * (HH * WW);
    float*       dst = g_xt + (size_t)b * (HH * WW) * CC;

    #pragma unroll
    for (int i = 0; i < 4; ++i) {
        int c = c0 + threadIdx.y + i * 8;
        tile[threadIdx.y + i * 8][threadIdx.x] = src[(size_t)c * (HH * WW) + hw0 + threadIdx.x];
    }
    __syncthreads();
    #pragma unroll
    for (int i = 0; i < 4; ++i) {
        int hw = hw0 + threadIdx.y + i * 8;
        dst[(size_t)hw * CC + c0 + threadIdx.x] = tile[threadIdx.x][threadIdx.y + i * 8];
    }
}

// ---------------- Kernel 2: ROI max-pool, warp-per-bin, float4 lanes ----------------
// Block = (k, cg in {0,1}, bin-row i in 0..6). 7 warps; warp j pools bin (i,j).
// Lane loads float4 = 4 consecutive channels; warp covers 128 channels.
__global__ __launch_bounds__(224) void roipool_warpbin_kernel(
    const float* __restrict__ rois,  // [K, 5]
    float* __restrict__ out)         // [K, C, 7, 7]
{
    __shared__ float stage[128 * PW];  // [c_local 0..127][j 0..6]

    int bid = blockIdx.x;
    int k   = bid / (2 * PH);
    int rem = bid - k * (2 * PH);
    int cg  = rem / PH;          // 128-channel half
    int i   = rem - cg * PH;     // bin row
    int j    = threadIdx.x >> 5; // warp -> bin col
    int lane = threadIdx.x & 31;

    const float* r = rois + k * 5;
    int b  = (int)r[0];
    // IEEE RN multiply (0.0625 exact), round half-to-even like jnp.round
    int x1 = (int)rintf(__fmul_rn(r[1], 0.0625f));
    int y1 = (int)rintf(__fmul_rn(r[2], 0.0625f));
    int x2 = (int)rintf(__fmul_rn(r[3], 0.0625f));
    int y2 = (int)rintf(__fmul_rn(r[4], 0.0625f));

    int roi_w = max(x2 - x1 + 1, 1);
    int roi_h = max(y2 - y1 + 1, 1);

    // XLA rewrites (x / 7) -> x * RN(1/7); RN(1/7) = 0x3E124925
    const float RECIP7 = __int_as_float(0x3E124925);
    float bw = __fmul_rn((float)roi_w, RECIP7);
    float bh = __fmul_rn((float)roi_h, RECIP7);

    int hs = min(max((int)floorf(__fmul_rn((float)i,       bh)) + y1, 0), HH);
    int he = min(max((int)ceilf (__fmul_rn((float)(i + 1), bh)) + y1, 0), HH);
    int ws = min(max((int)floorf(__fmul_rn((float)j,       bw)) + x1, 0), WW);
    int we = min(max((int)ceilf (__fmul_rn((float)(j + 1), bw)) + x1, 0), WW);

    float4 acc = make_float4(0.f, 0.f, 0.f, 0.f);
    if (hs < he && ws < we) {
        acc = make_float4(-FLT_MAX, -FLT_MAX, -FLT_MAX, -FLT_MAX);
        // base in float4 units: pixel p contributes at p*64 + lane
        const float4* base = (const float4*)(g_xt + (size_t)b * (HH * WW) * CC + cg * 128) + lane;
        for (int h = hs; h < he; ++h) {
            const float4* rowp = base + (size_t)(h * WW) * 64;
            int w = ws;
            for (; w + 3 < we; w += 4) {
                float4 v0 = __ldg(rowp + (size_t)(w    ) * 64);
                float4 v1 = __ldg(rowp + (size_t)(w + 1) * 64);
                float4 v2 = __ldg(rowp + (size_t)(w + 2) * 64);
                float4 v3 = __ldg(rowp + (size_t)(w + 3) * 64);
                acc.x = fmaxf(fmaxf(acc.x, v0.x), fmaxf(v1.x, fmaxf(v2.x, v3.x)));
                acc.y = fmaxf(fmaxf(acc.y, v0.y), fmaxf(v1.y, fmaxf(v2.y, v3.y)));
                acc.z = fmaxf(fmaxf(acc.z, v0.z), fmaxf(v1.z, fmaxf(v2.z, v3.z)));
                acc.w = fmaxf(fmaxf(acc.w, v0.w), fmaxf(v1.w, fmaxf(v2.w, v3.w)));
            }
            for (; w < we; ++w) {
                float4 v = __ldg(rowp + (size_t)w * 64);
                acc.x = fmaxf(acc.x, v.x);
                acc.y = fmaxf(acc.y, v.y);
                acc.z = fmaxf(acc.z, v.z);
                acc.w = fmaxf(acc.w, v.w);
            }
        }
    }

    int c0 = lane * 4;
    stage[(c0 + 0) * PW + j] = acc.x;
    stage[(c0 + 1) * PW + j] = acc.y;
    stage[(c0 + 2) * PW + j] = acc.z;
    stage[(c0 + 3) * PW + j] = acc.w;
    __syncthreads();

    // out[k, cg*128 + c, i, j]; channel stride = 49
    float* o = out + (size_t)k * (CC * PH * PW) + (size_t)cg * 128 * (PH * PW) + i * PW;
    for (int idx = threadIdx.x; idx < 128 * PW; idx += 224) {
        int c  = idx / PW;
        int jj = idx - c * PW;
        o[(size_t)c * (PH * PW) + jj] = stage[idx];
    }
}

extern "C" void kernel_launch(void* const* d_in, const int* in_sizes, int n_in,
                              void* d_out, int out_size)
{
    const float* x    = (const float*)d_in[0];
    const float* rois = (const float*)d_in[1];
    if (n_in >= 2 && in_sizes[0] < in_sizes[1]) {
        x    = (const float*)d_in[1];
        rois = (const float*)d_in[0];
    }
    float* out = (float*)d_out;

    dim3 tgrid(HH * WW / 32, CC / 32, NB);   // (128, 8, 2)
    dim3 tblk(32, 8);
    transpose_kernel<<<tgrid, tblk>>>(x);

    roipool_warpbin_kernel<<<KK * 2 * PH, 224>>>(rois, out);  // 1792 blocks
}